// round 1
// baseline (speedup 1.0000x reference)
#include <cuda_runtime.h>
#include <cuda_bf16.h>
#include <math.h>

// Problem constants (fixed by the dataset)
#define NPTS  16384
#define HDIM  256
#define KTOT  384          // 256 (coord branch) + 128 (dist branch)
#define G     128          // grid resolution
#define NCELL (G*G)
#define KNN   6            // k (hardcoded; dataset has k=6 -> keep 7 smallest incl. self)

// ---------------- scratch (static device globals; no allocation) ----------------
__device__ unsigned g_bbox[4];              // enc(minx), enc(maxx), enc(miny), enc(maxy)
__device__ int      g_counts[NCELL];
__device__ int      g_starts[NCELL];
__device__ int      g_cursor[NCELL];
__device__ int      g_cellof[NPTS];
__device__ float2   g_pts[NPTS];            // points sorted by cell
__device__ int      g_idx[NPTS];            // original index of sorted point
__device__ float    g_mean[NPTS];           // mean distance to 6 NN (original order)
__device__ float    g_A[NPTS * KTOT];       // activations [h1 | hd], row-major

// ---------------- helpers ----------------
__device__ __forceinline__ unsigned fenc(float f) {
    unsigned u = __float_as_uint(f);
    return (u & 0x80000000u) ? ~u : (u | 0x80000000u);
}
__device__ __forceinline__ float fdec(unsigned e) {
    unsigned u = (e & 0x80000000u) ? (e & 0x7FFFFFFFu) : ~e;
    return __uint_as_float(u);
}
__device__ __forceinline__ float silu_f(float x) {
    // x * sigmoid(x) = x / (1 + e^-x); EX2-based exp + RCP-based divide (~2ulp)
    return __fdividef(x, 1.0f + __expf(-x));
}

struct GridP { float minx, miny, sx, sy, invsx, invsy; };
__device__ __forceinline__ GridP load_grid() {
    GridP gp;
    float minx = fdec(g_bbox[0]), maxx = fdec(g_bbox[1]);
    float miny = fdec(g_bbox[2]), maxy = fdec(g_bbox[3]);
    float rx = maxx - minx, ry = maxy - miny;
    gp.minx = minx; gp.miny = miny;
    gp.sx = rx / (float)G;  gp.sy = ry / (float)G;
    gp.invsx = (rx > 0.f) ? (float)G / rx : 0.f;
    gp.invsy = (ry > 0.f) ? (float)G / ry : 0.f;
    return gp;
}
__device__ __forceinline__ int cell_x(const GridP& gp, float x) {
    int c = (int)((x - gp.minx) * gp.invsx);
    return min(G - 1, max(0, c));
}
__device__ __forceinline__ int cell_y(const GridP& gp, float y) {
    int c = (int)((y - gp.miny) * gp.invsy);
    return min(G - 1, max(0, c));
}

// ---------------- kernels ----------------
__global__ void k_init() {
    int i = blockIdx.x * blockDim.x + threadIdx.x;
    if (i < NCELL) g_counts[i] = 0;
    if (i == 0) {
        g_bbox[0] = 0xFFFFFFFFu; g_bbox[1] = 0u;
        g_bbox[2] = 0xFFFFFFFFu; g_bbox[3] = 0u;
    }
}

__global__ void k_bbox(const float2* __restrict__ coords) {
    int i = blockIdx.x * blockDim.x + threadIdx.x;
    float2 p = coords[i];
    unsigned ex = fenc(p.x), ey = fenc(p.y);
    unsigned mnx = ex, mxx = ex, mny = ey, mxy = ey;
    #pragma unroll
    for (int off = 16; off > 0; off >>= 1) {
        mnx = min(mnx, __shfl_xor_sync(0xFFFFFFFFu, mnx, off));
        mxx = max(mxx, __shfl_xor_sync(0xFFFFFFFFu, mxx, off));
        mny = min(mny, __shfl_xor_sync(0xFFFFFFFFu, mny, off));
        mxy = max(mxy, __shfl_xor_sync(0xFFFFFFFFu, mxy, off));
    }
    if ((threadIdx.x & 31) == 0) {
        atomicMin(&g_bbox[0], mnx); atomicMax(&g_bbox[1], mxx);
        atomicMin(&g_bbox[2], mny); atomicMax(&g_bbox[3], mxy);
    }
}

__global__ void k_count(const float2* __restrict__ coords) {
    int i = blockIdx.x * blockDim.x + threadIdx.x;
    GridP gp = load_grid();
    float2 p = coords[i];
    int c = cell_y(gp, p.y) * G + cell_x(gp, p.x);
    g_cellof[i] = c;
    atomicAdd(&g_counts[c], 1);
}

__global__ void k_scan() {
    __shared__ int part[1024];
    int t = threadIdx.x;
    int base = t * 16;
    int loc[16];
    int s = 0;
    #pragma unroll
    for (int j = 0; j < 16; j++) { loc[j] = s; s += g_counts[base + j]; }
    part[t] = s;
    __syncthreads();
    // Kogge-Stone inclusive scan
    for (int off = 1; off < 1024; off <<= 1) {
        int v = (t >= off) ? part[t - off] : 0;
        __syncthreads();
        part[t] += v;
        __syncthreads();
    }
    int pre = (t > 0) ? part[t - 1] : 0;
    #pragma unroll
    for (int j = 0; j < 16; j++) {
        int st = pre + loc[j];
        g_starts[base + j] = st;
        g_cursor[base + j] = st;
    }
}

__global__ void k_scatter(const float2* __restrict__ coords) {
    int i = blockIdx.x * blockDim.x + threadIdx.x;
    int c = g_cellof[i];
    int pos = atomicAdd(&g_cursor[c], 1);
    g_pts[pos] = coords[i];
    g_idx[pos] = i;
}

__global__ void k_knn() {
    int i = blockIdx.x * blockDim.x + threadIdx.x;
    if (i >= NPTS) return;
    GridP gp = load_grid();
    float2 q = g_pts[i];                  // sorted order -> warp-coherent rings
    int cx = cell_x(gp, q.x), cy = cell_y(gp, q.y);

    float best[KNN + 1];
    #pragma unroll
    for (int t = 0; t <= KNN; t++) best[t] = 3.4e38f;

    auto scan_cell = [&](int xx, int yy) {
        int c = yy * G + xx;
        int s0 = g_starts[c];
        int e0 = s0 + g_counts[c];
        for (int j = s0; j < e0; j++) {
            float2 p = g_pts[j];
            float dx = q.x - p.x;
            float dy = q.y - p.y;
            float d2 = fmaf(dx, dx, dy * dy);
            if (d2 < best[KNN]) {
                best[KNN] = d2;
                #pragma unroll
                for (int t = KNN; t > 0; t--) {
                    if (best[t] < best[t - 1]) {
                        float tm = best[t - 1]; best[t - 1] = best[t]; best[t] = tm;
                    }
                }
            }
        }
    };

    int r = 0;
    while (true) {
        int xlo = cx - r, xhi = cx + r, ylo = cy - r, yhi = cy + r;
        if (r == 0) {
            scan_cell(cx, cy);
        } else {
            int xa = max(xlo, 0), xb = min(xhi, G - 1);
            if (ylo >= 0)     for (int xx = xa; xx <= xb; xx++) scan_cell(xx, ylo);
            if (yhi <= G - 1) for (int xx = xa; xx <= xb; xx++) scan_cell(xx, yhi);
            int ya = max(ylo + 1, 0), yb = min(yhi - 1, G - 1);
            for (int yy = ya; yy <= yb; yy++) {
                if (xlo >= 0)     scan_cell(xlo, yy);
                if (xhi <= G - 1) scan_cell(xhi, yy);
            }
        }
        bool covered = (xlo <= 0) && (ylo <= 0) && (xhi >= G - 1) && (yhi >= G - 1);
        if (covered) break;
        // conservative distance to nearest uncovered region (with safety margin)
        float bnd = 3.4e38f;
        if (xlo > 0)     bnd = fminf(bnd, q.x - (gp.minx + (float)xlo * gp.sx));
        if (xhi < G - 1) bnd = fminf(bnd, (gp.minx + (float)(xhi + 1) * gp.sx) - q.x);
        if (ylo > 0)     bnd = fminf(bnd, q.y - (gp.miny + (float)ylo * gp.sy));
        if (yhi < G - 1) bnd = fminf(bnd, (gp.miny + (float)(yhi + 1) * gp.sy) - q.y);
        bnd -= 1e-4f;
        if (bnd > 0.f && best[KNN] <= bnd * bnd) break;
        r++;
    }

    // mean of ranks 1..6 of sqrt(max(d2,1e-12)) (rank 0 = self, ~0)
    float s = 0.f;
    #pragma unroll
    for (int t = 1; t <= KNN; t++) s += sqrtf(fmaxf(best[t], 1e-12f));
    g_mean[g_idx[i]] = s * (1.0f / (float)KNN);
}

// Activation precompute: A[m][0..255] = silu(x@W1+b1), A[m][256..383] = silu(m*Wd1+bd1)
__global__ void k_act(const float2* __restrict__ coords,
                      const float* __restrict__ W1, const float* __restrict__ b1,
                      const float* __restrict__ Wd1, const float* __restrict__ bd1) {
    int idx = blockIdx.x * blockDim.x + threadIdx.x;   // NPTS * 96 threads, 4 elems each
    int m  = idx / (KTOT / 4);
    int kq = (idx % (KTOT / 4)) * 4;
    float4 o;
    if (kq < 256) {
        float2 x  = coords[m];
        float4 w0 = *(const float4*)(W1 + kq);          // W1[0][kq..kq+3]
        float4 w1 = *(const float4*)(W1 + 256 + kq);    // W1[1][kq..kq+3]
        float4 bb = *(const float4*)(b1 + kq);
        o.x = silu_f(fmaf(x.x, w0.x, fmaf(x.y, w1.x, bb.x)));
        o.y = silu_f(fmaf(x.x, w0.y, fmaf(x.y, w1.y, bb.y)));
        o.z = silu_f(fmaf(x.x, w0.z, fmaf(x.y, w1.z, bb.z)));
        o.w = silu_f(fmaf(x.x, w0.w, fmaf(x.y, w1.w, bb.w)));
    } else {
        int j = kq - 256;
        float md  = g_mean[m];
        float4 w  = *(const float4*)(Wd1 + j);
        float4 bb = *(const float4*)(bd1 + j);
        o.x = silu_f(fmaf(md, w.x, bb.x));
        o.y = silu_f(fmaf(md, w.y, bb.y));
        o.z = silu_f(fmaf(md, w.z, bb.z));
        o.w = silu_f(fmaf(md, w.w, bb.w));
    }
    *(float4*)(g_A + m * KTOT + kq) = o;
}

// GEMM: out[16384,256] = A[16384,384] @ [W2;Wd2][384,256] + (b2+bd2)
#define TM 128
#define TN 64
#define TK 16
__global__ __launch_bounds__(256) void k_gemm(
    const float* __restrict__ W2, const float* __restrict__ Wd2,
    const float* __restrict__ b2, const float* __restrict__ bd2,
    float* __restrict__ out)
{
    __shared__ __align__(16) float As[TK * 132];   // padded stride 132
    __shared__ __align__(16) float Bs[TK * TN];
    int tx = threadIdx.x, ty = threadIdx.y;        // 16 x 16
    int tid = ty * 16 + tx;
    int m0 = blockIdx.y * TM;
    int n0 = blockIdx.x * TN;

    float acc[8][4];
    #pragma unroll
    for (int i = 0; i < 8; i++)
        #pragma unroll
        for (int j = 0; j < 4; j++) acc[i][j] = 0.f;

    for (int k0 = 0; k0 < KTOT; k0 += TK) {
        // stage A: 128x16 -> As[k][m] (transposed)
        #pragma unroll
        for (int qq = 0; qq < 2; qq++) {
            int q = tid * 2 + qq;
            int r = q >> 2;
            int c = (q & 3) * 4;
            float4 v = *(const float4*)(g_A + (m0 + r) * KTOT + k0 + c);
            As[(c + 0) * 132 + r] = v.x;
            As[(c + 1) * 132 + r] = v.y;
            As[(c + 2) * 132 + r] = v.z;
            As[(c + 3) * 132 + r] = v.w;
        }
        // stage B: 16x64
        {
            int r = tid >> 4;
            int c = (tid & 15) * 4;
            const float* Bsrc = (k0 < 256) ? (W2 + (k0 + r) * HDIM)
                                           : (Wd2 + (k0 - 256 + r) * HDIM);
            float4 v = *(const float4*)(Bsrc + n0 + c);
            *(float4*)(Bs + r * TN + c) = v;
        }
        __syncthreads();
        #pragma unroll
        for (int kk = 0; kk < TK; kk++) {
            float4 a0 = *(const float4*)(As + kk * 132 + ty * 8);
            float4 a1 = *(const float4*)(As + kk * 132 + ty * 8 + 4);
            float4 b  = *(const float4*)(Bs + kk * TN + tx * 4);
            float av[8] = {a0.x, a0.y, a0.z, a0.w, a1.x, a1.y, a1.z, a1.w};
            float bv[4] = {b.x, b.y, b.z, b.w};
            #pragma unroll
            for (int i = 0; i < 8; i++)
                #pragma unroll
                for (int j = 0; j < 4; j++)
                    acc[i][j] = fmaf(av[i], bv[j], acc[i][j]);
        }
        __syncthreads();
    }

    float4 bb2 = *(const float4*)(b2 + n0 + tx * 4);
    float4 bbd = *(const float4*)(bd2 + n0 + tx * 4);
    float4 bias = make_float4(bb2.x + bbd.x, bb2.y + bbd.y, bb2.z + bbd.z, bb2.w + bbd.w);
    #pragma unroll
    for (int i = 0; i < 8; i++) {
        int row = m0 + ty * 8 + i;
        float4 o = make_float4(acc[i][0] + bias.x, acc[i][1] + bias.y,
                               acc[i][2] + bias.z, acc[i][3] + bias.w);
        *(float4*)(out + row * HDIM + n0 + tx * 4) = o;
    }
}

// ---------------- launch ----------------
extern "C" void kernel_launch(void* const* d_in, const int* in_sizes, int n_in,
                              void* d_out, int out_size) {
    const float2* coords = (const float2*)d_in[0];
    const float*  W1  = (const float*)d_in[1];
    const float*  b1  = (const float*)d_in[2];
    const float*  W2  = (const float*)d_in[3];
    const float*  b2  = (const float*)d_in[4];
    const float*  Wd1 = (const float*)d_in[5];
    const float*  bd1 = (const float*)d_in[6];
    const float*  Wd2 = (const float*)d_in[7];
    const float*  bd2 = (const float*)d_in[8];
    float* out = (float*)d_out;

    k_init   <<<NCELL / 256, 256>>>();
    k_bbox   <<<NPTS / 256, 256>>>(coords);
    k_count  <<<NPTS / 256, 256>>>(coords);
    k_scan   <<<1, 1024>>>();
    k_scatter<<<NPTS / 256, 256>>>(coords);
    k_knn    <<<NPTS / 128, 128>>>();
    k_act    <<<(NPTS * (KTOT / 4)) / 256, 256>>>(coords, W1, b1, Wd1, bd1);
    k_gemm   <<<dim3(HDIM / TN, NPTS / TM), dim3(16, 16)>>>(W2, Wd2, b2, bd2, out);
}

// round 2
// speedup vs baseline: 1.0822x; 1.0822x over previous
#include <cuda_runtime.h>
#include <cuda_bf16.h>
#include <math.h>

// Problem constants (fixed by the dataset)
#define NPTS  16384
#define HDIM  256
#define KTOT  384          // 256 (coord branch) + 128 (dist branch)
#define G     128          // grid resolution
#define NCELL (G*G)
#define KNN   6

// ---------------- scratch (static device globals; no allocation) ----------------
__device__ unsigned g_bbox[4];
__device__ int      g_counts[NCELL];
__device__ int      g_starts[NCELL];
__device__ int      g_cursor[NCELL];
__device__ int      g_cellof[NPTS];
__device__ float2   g_pts[NPTS];
__device__ int      g_idx[NPTS];
__device__ float    g_mean[NPTS];
__device__ float    g_A[NPTS * KTOT];       // activations [h1 | hd], row-major

// ---------------- helpers ----------------
__device__ __forceinline__ unsigned fenc(float f) {
    unsigned u = __float_as_uint(f);
    return (u & 0x80000000u) ? ~u : (u | 0x80000000u);
}
__device__ __forceinline__ float fdec(unsigned e) {
    unsigned u = (e & 0x80000000u) ? (e & 0x7FFFFFFFu) : ~e;
    return __uint_as_float(u);
}
__device__ __forceinline__ float silu_f(float x) {
    return __fdividef(x, 1.0f + __expf(-x));
}

// f32x2 packed FMA (Blackwell double-rate fp32 path; only reachable via PTX)
typedef unsigned long long ull;
__device__ __forceinline__ void fma2(ull& d, ull a, ull b) {
    asm("fma.rn.f32x2 %0, %1, %2, %3;" : "=l"(d) : "l"(a), "l"(b), "l"(d));
}
__device__ __forceinline__ ull pack2(float x) {
    ull r; asm("mov.b64 %0, {%1, %1};" : "=l"(r) : "f"(x)); return r;
}
__device__ __forceinline__ void unpack2(ull v, float& lo, float& hi) {
    asm("mov.b64 {%0, %1}, %2;" : "=f"(lo), "=f"(hi) : "l"(v));
}

struct GridP { float minx, miny, sx, sy, invsx, invsy; };
__device__ __forceinline__ GridP load_grid() {
    GridP gp;
    float minx = fdec(g_bbox[0]), maxx = fdec(g_bbox[1]);
    float miny = fdec(g_bbox[2]), maxy = fdec(g_bbox[3]);
    float rx = maxx - minx, ry = maxy - miny;
    gp.minx = minx; gp.miny = miny;
    gp.sx = rx / (float)G;  gp.sy = ry / (float)G;
    gp.invsx = (rx > 0.f) ? (float)G / rx : 0.f;
    gp.invsy = (ry > 0.f) ? (float)G / ry : 0.f;
    return gp;
}
__device__ __forceinline__ int cell_x(const GridP& gp, float x) {
    int c = (int)((x - gp.minx) * gp.invsx);
    return min(G - 1, max(0, c));
}
__device__ __forceinline__ int cell_y(const GridP& gp, float y) {
    int c = (int)((y - gp.miny) * gp.invsy);
    return min(G - 1, max(0, c));
}

// ---------------- kernels ----------------
__global__ void k_init() {
    int i = blockIdx.x * blockDim.x + threadIdx.x;
    if (i < NCELL) g_counts[i] = 0;
    if (i == 0) {
        g_bbox[0] = 0xFFFFFFFFu; g_bbox[1] = 0u;
        g_bbox[2] = 0xFFFFFFFFu; g_bbox[3] = 0u;
    }
}

__global__ void k_bbox(const float2* __restrict__ coords) {
    int i = blockIdx.x * blockDim.x + threadIdx.x;
    float2 p = coords[i];
    unsigned ex = fenc(p.x), ey = fenc(p.y);
    unsigned mnx = ex, mxx = ex, mny = ey, mxy = ey;
    #pragma unroll
    for (int off = 16; off > 0; off >>= 1) {
        mnx = min(mnx, __shfl_xor_sync(0xFFFFFFFFu, mnx, off));
        mxx = max(mxx, __shfl_xor_sync(0xFFFFFFFFu, mxx, off));
        mny = min(mny, __shfl_xor_sync(0xFFFFFFFFu, mny, off));
        mxy = max(mxy, __shfl_xor_sync(0xFFFFFFFFu, mxy, off));
    }
    if ((threadIdx.x & 31) == 0) {
        atomicMin(&g_bbox[0], mnx); atomicMax(&g_bbox[1], mxx);
        atomicMin(&g_bbox[2], mny); atomicMax(&g_bbox[3], mxy);
    }
}

__global__ void k_count(const float2* __restrict__ coords) {
    int i = blockIdx.x * blockDim.x + threadIdx.x;
    GridP gp = load_grid();
    float2 p = coords[i];
    int c = cell_y(gp, p.y) * G + cell_x(gp, p.x);
    g_cellof[i] = c;
    atomicAdd(&g_counts[c], 1);
}

// Warp-shuffle scan: 2 barriers instead of 20.
__global__ void k_scan() {
    __shared__ int wsum[32];
    int t = threadIdx.x;               // 1024 threads, 16 cells each
    int lane = t & 31, warp = t >> 5;
    int base = t * 16;
    int4 c0 = *(const int4*)(g_counts + base + 0);
    int4 c1 = *(const int4*)(g_counts + base + 4);
    int4 c2 = *(const int4*)(g_counts + base + 8);
    int4 c3 = *(const int4*)(g_counts + base + 12);
    int v[16] = {c0.x,c0.y,c0.z,c0.w, c1.x,c1.y,c1.z,c1.w,
                 c2.x,c2.y,c2.z,c2.w, c3.x,c3.y,c3.z,c3.w};
    int loc[16]; int s = 0;
    #pragma unroll
    for (int j = 0; j < 16; j++) { loc[j] = s; s += v[j]; }
    // inclusive warp scan of per-thread totals
    int inc = s;
    #pragma unroll
    for (int off = 1; off < 32; off <<= 1) {
        int n = __shfl_up_sync(0xFFFFFFFFu, inc, off);
        if (lane >= off) inc += n;
    }
    if (lane == 31) wsum[warp] = inc;
    __syncthreads();
    if (warp == 0) {
        int w = wsum[lane];
        #pragma unroll
        for (int off = 1; off < 32; off <<= 1) {
            int n = __shfl_up_sync(0xFFFFFFFFu, w, off);
            if (lane >= off) w += n;
        }
        wsum[lane] = w;
    }
    __syncthreads();
    int pre = ((warp > 0) ? wsum[warp - 1] : 0) + (inc - s);  // exclusive prefix
    int o[16];
    #pragma unroll
    for (int j = 0; j < 16; j++) o[j] = pre + loc[j];
    #pragma unroll
    for (int q = 0; q < 4; q++) {
        int4 w4 = make_int4(o[q*4], o[q*4+1], o[q*4+2], o[q*4+3]);
        *(int4*)(g_starts + base + q*4) = w4;
        *(int4*)(g_cursor + base + q*4) = w4;
    }
}

__global__ void k_scatter(const float2* __restrict__ coords) {
    int i = blockIdx.x * blockDim.x + threadIdx.x;
    int c = g_cellof[i];
    int pos = atomicAdd(&g_cursor[c], 1);
    g_pts[pos] = coords[i];
    g_idx[pos] = i;
}

__global__ void k_knn() {
    int i = blockIdx.x * blockDim.x + threadIdx.x;
    if (i >= NPTS) return;
    GridP gp = load_grid();
    float2 q = g_pts[i];
    int cx = cell_x(gp, q.x), cy = cell_y(gp, q.y);

    float best[KNN + 1];
    #pragma unroll
    for (int t = 0; t <= KNN; t++) best[t] = 3.4e38f;

    auto scan_cell = [&](int xx, int yy) {
        int c = yy * G + xx;
        int s0 = g_starts[c];
        int e0 = s0 + g_counts[c];
        for (int j = s0; j < e0; j++) {
            float2 p = g_pts[j];
            float dx = q.x - p.x;
            float dy = q.y - p.y;
            float d2 = fmaf(dx, dx, dy * dy);
            if (d2 < best[KNN]) {
                best[KNN] = d2;
                #pragma unroll
                for (int t = KNN; t > 0; t--) {
                    if (best[t] < best[t - 1]) {
                        float tm = best[t - 1]; best[t - 1] = best[t]; best[t] = tm;
                    }
                }
            }
        }
    };

    int r = 0;
    while (true) {
        int xlo = cx - r, xhi = cx + r, ylo = cy - r, yhi = cy + r;
        if (r == 0) {
            scan_cell(cx, cy);
        } else {
            int xa = max(xlo, 0), xb = min(xhi, G - 1);
            if (ylo >= 0)     for (int xx = xa; xx <= xb; xx++) scan_cell(xx, ylo);
            if (yhi <= G - 1) for (int xx = xa; xx <= xb; xx++) scan_cell(xx, yhi);
            int ya = max(ylo + 1, 0), yb = min(yhi - 1, G - 1);
            for (int yy = ya; yy <= yb; yy++) {
                if (xlo >= 0)     scan_cell(xlo, yy);
                if (xhi <= G - 1) scan_cell(xhi, yy);
            }
        }
        bool covered = (xlo <= 0) && (ylo <= 0) && (xhi >= G - 1) && (yhi >= G - 1);
        if (covered) break;
        float bnd = 3.4e38f;
        if (xlo > 0)     bnd = fminf(bnd, q.x - (gp.minx + (float)xlo * gp.sx));
        if (xhi < G - 1) bnd = fminf(bnd, (gp.minx + (float)(xhi + 1) * gp.sx) - q.x);
        if (ylo > 0)     bnd = fminf(bnd, q.y - (gp.miny + (float)ylo * gp.sy));
        if (yhi < G - 1) bnd = fminf(bnd, (gp.miny + (float)(yhi + 1) * gp.sy) - q.y);
        bnd -= 1e-4f;
        if (bnd > 0.f && best[KNN] <= bnd * bnd) break;
        r++;
    }

    float s = 0.f;
    #pragma unroll
    for (int t = 1; t <= KNN; t++) s += sqrtf(fmaxf(best[t], 1e-12f));
    g_mean[g_idx[i]] = s * (1.0f / (float)KNN);
}

// Activation precompute: A[m][0..255] = silu(x@W1+b1), A[m][256..383] = silu(m*Wd1+bd1)
__global__ void k_act(const float2* __restrict__ coords,
                      const float* __restrict__ W1, const float* __restrict__ b1,
                      const float* __restrict__ Wd1, const float* __restrict__ bd1) {
    int idx = blockIdx.x * blockDim.x + threadIdx.x;
    int m  = idx / (KTOT / 4);
    int kq = (idx % (KTOT / 4)) * 4;
    float4 o;
    if (kq < 256) {
        float2 x  = coords[m];
        float4 w0 = *(const float4*)(W1 + kq);
        float4 w1 = *(const float4*)(W1 + 256 + kq);
        float4 bb = *(const float4*)(b1 + kq);
        o.x = silu_f(fmaf(x.x, w0.x, fmaf(x.y, w1.x, bb.x)));
        o.y = silu_f(fmaf(x.x, w0.y, fmaf(x.y, w1.y, bb.y)));
        o.z = silu_f(fmaf(x.x, w0.z, fmaf(x.y, w1.z, bb.z)));
        o.w = silu_f(fmaf(x.x, w0.w, fmaf(x.y, w1.w, bb.w)));
    } else {
        int j = kq - 256;
        float md  = g_mean[m];
        float4 w  = *(const float4*)(Wd1 + j);
        float4 bb = *(const float4*)(bd1 + j);
        o.x = silu_f(fmaf(md, w.x, bb.x));
        o.y = silu_f(fmaf(md, w.y, bb.y));
        o.z = silu_f(fmaf(md, w.z, bb.z));
        o.w = silu_f(fmaf(md, w.w, bb.w));
    }
    *(float4*)(g_A + m * KTOT + kq) = o;
}

// GEMM: out[16384,256] = A[16384,384] @ [W2;Wd2][384,256] + (b2+bd2)
// FFMA2 (f32x2) version: TM=TN=128, TK=16, 256 threads, 8x8 per-thread tile.
#define TM 128
#define TN 128
#define TK 16
#define AS_STR 132
__global__ __launch_bounds__(256, 2) void k_gemm(
    const float* __restrict__ W2, const float* __restrict__ Wd2,
    const float* __restrict__ b2, const float* __restrict__ bd2,
    float* __restrict__ out)
{
    __shared__ __align__(16) float As[TK * AS_STR];   // [k][m], padded
    __shared__ __align__(16) float Bs[TK * TN];       // [k][n]
    int tx = threadIdx.x & 15, ty = threadIdx.x >> 4;
    int tid = threadIdx.x;
    int m0 = blockIdx.y * TM;
    int n0 = blockIdx.x * TN;

    ull acc[4][8];   // 4 row-pairs x 8 cols, f32x2 over (even,odd) rows
    #pragma unroll
    for (int i = 0; i < 4; i++)
        #pragma unroll
        for (int j = 0; j < 8; j++) acc[i][j] = 0ull;

    // staging indices
    int ar = tid >> 1;            // A row within tile (0..127)
    int ah = (tid & 1) * 8;       // A k-offset (0 or 8)
    int br = tid >> 4;            // B row within tile (0..15)
    int bc = (tid & 15) * 8;      // B col (0..120 step 8)

    for (int k0 = 0; k0 < KTOT; k0 += TK) {
        // stage A: 128x16 -> As[k][m] (transposed)
        {
            const float* src = g_A + (m0 + ar) * KTOT + k0 + ah;
            float4 v0 = *(const float4*)(src);
            float4 v1 = *(const float4*)(src + 4);
            As[(ah + 0) * AS_STR + ar] = v0.x;
            As[(ah + 1) * AS_STR + ar] = v0.y;
            As[(ah + 2) * AS_STR + ar] = v0.z;
            As[(ah + 3) * AS_STR + ar] = v0.w;
            As[(ah + 4) * AS_STR + ar] = v1.x;
            As[(ah + 5) * AS_STR + ar] = v1.y;
            As[(ah + 6) * AS_STR + ar] = v1.z;
            As[(ah + 7) * AS_STR + ar] = v1.w;
        }
        // stage B: 16x128
        {
            const float* Bsrc = (k0 < 256) ? (W2 + (k0 + br) * HDIM)
                                           : (Wd2 + (k0 - 256 + br) * HDIM);
            float4 v0 = *(const float4*)(Bsrc + n0 + bc);
            float4 v1 = *(const float4*)(Bsrc + n0 + bc + 4);
            *(float4*)(Bs + br * TN + bc)     = v0;
            *(float4*)(Bs + br * TN + bc + 4) = v1;
        }
        __syncthreads();
        #pragma unroll
        for (int kk = 0; kk < TK; kk++) {
            // a-pairs: adjacent rows already contiguous -> direct f32x2 loads
            ulonglong2 a01 = *(const ulonglong2*)(As + kk * AS_STR + ty * 8);
            ulonglong2 a23 = *(const ulonglong2*)(As + kk * AS_STR + ty * 8 + 4);
            ull av[4] = {a01.x, a01.y, a23.x, a23.y};
            float4 bq0 = *(const float4*)(Bs + kk * TN + tx * 8);
            float4 bq1 = *(const float4*)(Bs + kk * TN + tx * 8 + 4);
            ull bv[8] = {pack2(bq0.x), pack2(bq0.y), pack2(bq0.z), pack2(bq0.w),
                         pack2(bq1.x), pack2(bq1.y), pack2(bq1.z), pack2(bq1.w)};
            #pragma unroll
            for (int i = 0; i < 4; i++)
                #pragma unroll
                for (int j = 0; j < 8; j++)
                    fma2(acc[i][j], av[i], bv[j]);
        }
        __syncthreads();
    }

    // bias (b2 + bd2) for 8 cols
    float bias[8];
    {
        float4 p0 = *(const float4*)(b2  + n0 + tx * 8);
        float4 p1 = *(const float4*)(b2  + n0 + tx * 8 + 4);
        float4 q0 = *(const float4*)(bd2 + n0 + tx * 8);
        float4 q1 = *(const float4*)(bd2 + n0 + tx * 8 + 4);
        bias[0]=p0.x+q0.x; bias[1]=p0.y+q0.y; bias[2]=p0.z+q0.z; bias[3]=p0.w+q0.w;
        bias[4]=p1.x+q1.x; bias[5]=p1.y+q1.y; bias[6]=p1.z+q1.z; bias[7]=p1.w+q1.w;
    }
    #pragma unroll
    for (int i = 0; i < 4; i++) {
        int r0 = m0 + ty * 8 + 2 * i;
        float o0[8], o1[8];
        #pragma unroll
        for (int j = 0; j < 8; j++) {
            float lo, hi; unpack2(acc[i][j], lo, hi);
            o0[j] = lo + bias[j];
            o1[j] = hi + bias[j];
        }
        float* d0 = out + r0 * HDIM + n0 + tx * 8;
        float* d1 = d0 + HDIM;
        *(float4*)(d0)     = make_float4(o0[0], o0[1], o0[2], o0[3]);
        *(float4*)(d0 + 4) = make_float4(o0[4], o0[5], o0[6], o0[7]);
        *(float4*)(d1)     = make_float4(o1[0], o1[1], o1[2], o1[3]);
        *(float4*)(d1 + 4) = make_float4(o1[4], o1[5], o1[6], o1[7]);
    }
}

// ---------------- launch ----------------
extern "C" void kernel_launch(void* const* d_in, const int* in_sizes, int n_in,
                              void* d_out, int out_size) {
    const float2* coords = (const float2*)d_in[0];
    const float*  W1  = (const float*)d_in[1];
    const float*  b1  = (const float*)d_in[2];
    const float*  W2  = (const float*)d_in[3];
    const float*  b2  = (const float*)d_in[4];
    const float*  Wd1 = (const float*)d_in[5];
    const float*  bd1 = (const float*)d_in[6];
    const float*  Wd2 = (const float*)d_in[7];
    const float*  bd2 = (const float*)d_in[8];
    float* out = (float*)d_out;

    k_init   <<<NCELL / 256, 256>>>();
    k_bbox   <<<NPTS / 256, 256>>>(coords);
    k_count  <<<NPTS / 256, 256>>>(coords);
    k_scan   <<<1, 1024>>>();
    k_scatter<<<NPTS / 256, 256>>>(coords);
    k_knn    <<<NPTS / 128, 128>>>();
    k_act    <<<(NPTS * (KTOT / 4)) / 256, 256>>>(coords, W1, b1, Wd1, bd1);
    k_gemm   <<<dim3(HDIM / TN, NPTS / TM), dim3(256)>>>(W2, Wd2, b2, bd2, out);
}